// round 13
// baseline (speedup 1.0000x reference)
#include <cuda_runtime.h>
#include <cuda_bf16.h>
#include <math.h>
#include <stdint.h>

#define N_PTS   8192
#define D_DIM   8
#define K_DIM   64
#define Q_DIM   16
#define KQ      1024
#define TWO_PI  6.283185307179586f

#define EPHI_SZ (N_PTS * KQ)    // 8388608
#define G_SZ    (KQ * KQ)       // 1048576
// d_out layout: [E_phi (N,KQ) | G (KQ,KQ) | E_cos_sq (N,KQ)]

// -------- device scratch --------
__device__ float g_dpart[256 * KQ];
__device__ __nv_bfloat16 g_hi[(size_t)KQ * N_PTS];
__device__ __nv_bfloat16 g_lo[(size_t)KQ * N_PTS];

// ---------------------------------------------------------------------------
// helpers
// ---------------------------------------------------------------------------
__device__ __forceinline__ uint32_t smem_u32(const void* p) {
    uint32_t a;
    asm("{ .reg .u64 t; cvta.to.shared.u64 t, %1; cvt.u32.u64 %0, t; }"
        : "=r"(a) : "l"(p));
    return a;
}
__device__ __forceinline__ void cp16(uint32_t dst, const void* src) {
    asm volatile("cp.async.cg.shared.global [%0], [%1], 16;"
                 :: "r"(dst), "l"(src));
}
__device__ __forceinline__ void cp_commit() {
    asm volatile("cp.async.commit_group;" ::: "memory");
}
template <int N>
__device__ __forceinline__ void cp_wait() {
    asm volatile("cp.async.wait_group %0;" :: "n"(N) : "memory");
}
__device__ __forceinline__ void ldsm4(uint32_t* r, uint32_t addr) {
    asm volatile("ldmatrix.sync.aligned.m8n8.x4.shared.b16 {%0,%1,%2,%3}, [%4];"
                 : "=r"(r[0]), "=r"(r[1]), "=r"(r[2]), "=r"(r[3]) : "r"(addr));
}
__device__ __forceinline__ void mma_bf16(float* c, const uint32_t* a,
                                         uint32_t b0, uint32_t b1) {
    asm volatile(
        "mma.sync.aligned.m16n8k16.row.col.f32.bf16.bf16.f32 "
        "{%0,%1,%2,%3}, {%4,%5,%6,%7}, {%8,%9}, {%0,%1,%2,%3};"
        : "+f"(c[0]), "+f"(c[1]), "+f"(c[2]), "+f"(c[3])
        : "r"(a[0]), "r"(a[1]), "r"(a[2]), "r"(a[3]), "r"(b0), "r"(b1));
}

// swizzled offset within a 32B-row warp-private buffer (16B granules)
// conflict-free for ldsm phases and LDGSTS: group = (2*row + seg') mod 8
__device__ __forceinline__ uint32_t swz32(int row, int seg) {
    return (uint32_t)(row * 32 + ((seg ^ ((row >> 2) & 1)) << 4));
}

// ---------------------------------------------------------------------------
// Kernel 1: fused E_phi, E_cos_sq, split-bf16 transposed hi/lo, diag partials.
// ---------------------------------------------------------------------------
__global__ void __launch_bounds__(256) ephi_kernel(const float* __restrict__ X,
                            const float* __restrict__ z,
                            const float* __restrict__ weight,
                            const float* __restrict__ mu,
                            const float* __restrict__ stdv,
                            const float* __restrict__ alpha,
                            const float* __restrict__ var_mu_w,
                            const float* __restrict__ var_sigma_w,
                            float* __restrict__ out)
{
    const int tid = threadIdx.x;
    const int kq0 = blockIdx.x * 256;
    const int kq  = kq0 + tid;
    const int n0  = blockIdx.y * 32;

    __shared__ float Xs[256];
    __shared__ float s_mp[128], s_sp[128];     // mean_p, std_p per (d,q)
    __shared__ __nv_bfloat16 s_hi[256][34];
    __shared__ __nv_bfloat16 s_lo[256][34];

    Xs[tid] = TWO_PI * X[n0 * D_DIM + tid];
    if (tid < 128) {
        s_mp[tid] = 1.0f / (mu[tid] + 1e-8f);
        s_sp[tid] = 1.0f / (TWO_PI * stdv[tid] + 1e-8f);
    }
    __syncthreads();

    const int q = kq & (Q_DIM - 1);
    float ew[D_DIM], cc[D_DIM], zz[D_DIM];
#pragma unroll
    for (int d = 0; d < D_DIM; ++d) {
        const float mp = s_mp[d * Q_DIM + q];
        const float sp = s_sp[d * Q_DIM + q];
        ew[d] = mp + sp * var_mu_w[d * KQ + kq];
        cc[d] = sp * sp * var_sigma_w[d * KQ + kq];
        zz[d] = TWO_PI * z[d * KQ + kq];
    }
    const float a    = alpha[kq];
    const float coef = 2.0f * weight[q] * (1.0f / (float)K_DIM);
    const float sq   = sqrtf(coef);

    float* __restrict__ outE = out;
    float* __restrict__ outC = out + EPHI_SZ + G_SZ;

    float dsum = 0.0f;
#pragma unroll 4
    for (int r = 0; r < 32; ++r) {
        float phase = 0.0f, s = 0.0f;
#pragma unroll
        for (int d = 0; d < D_DIM; ++d) {
            float xb = Xs[r * D_DIM + d] - zz[d];
            phase = fmaf(xb, ew[d], phase);
            s     = fmaf(cc[d], xb * xb, s);
        }
        float cw    = __cosf(a + phase);
        float decay = __expf(-0.5f * s);

        const int n = n0 + r;
        float E = sq * decay * cw;
        outE[n * KQ + kq] = E;

        float d2  = decay * decay;
        float d4  = d2 * d2;
        float c2w = 2.0f * cw * cw - 1.0f;
        float ecs = coef * (0.5f + 0.5f * d4 * c2w);
        outC[n * KQ + kq] = ecs;
        dsum += ecs;

        __nv_bfloat16 h = __float2bfloat16(E);
        s_hi[tid][r] = h;
        s_lo[tid][r] = __float2bfloat16(E - __bfloat162float(h));
    }
    g_dpart[blockIdx.y * KQ + kq] = dsum;
    __syncthreads();

    uint32_t* __restrict__ H = (uint32_t*)g_hi;
    uint32_t* __restrict__ L = (uint32_t*)g_lo;
#pragma unroll
    for (int i = 0; i < 16; ++i) {
        int v   = tid + i * 256;
        int row = v >> 4;
        int seg = v & 15;
        uint32_t h2 = *(const uint32_t*)&s_hi[row][seg * 2];
        uint32_t l2 = *(const uint32_t*)&s_lo[row][seg * 2];
        size_t o = ((size_t)(kq0 + row) * N_PTS + n0) / 2 + seg;
        H[o] = h2;
        L[o] = l2;
    }
}

// ---------------------------------------------------------------------------
// Kernel 2: SYRK, warp-autonomous pipelines, 2 CTAs/SM (4 warps/SMSP).
// 272 tiles of 64(i) x 32(j) covering tj*32 >= ti*64 (upper). 256 threads =
// 8 warps: ms = m-half (32 rows), kset = k-quarter (16 of 64 k per chunk).
// Warp-private smem: stage = AHI 1KB | ALO 1KB | BHI 1KB | BLO 1KB = 4KB,
// double buffered -> 8KB/warp, 64KB/CTA -> 2 CTAs resident per SM.
// 128 chunks of 64 k. R8-proven order: batched ldsm, hh chain, refill+commit,
// hl chain, lh chain. NO mainloop __syncthreads.
// Epilogue: 4-set smem reduce + write/mirror; diagonal tiles splice g_dpart.
// ---------------------------------------------------------------------------
#define A_HI_OFF 0
#define A_LO_OFF 1024
#define B_HI_OFF 2048
#define B_LO_OFF 3072
#define WSTAGE   4096
#define WBUF     (2 * WSTAGE)        // 8192 per warp
#define SMEM_SYRK (8 * WBUF)         // 65536
#define NSC 128
#define RED_SET  (32 * 33 * 4)       // 4224 bytes per (kset,ms) stash
#define SDIAG_OFF (6 * RED_SET)      // 25344

// refill one 4KB stage: 4 buffers x 64 chunks(32 rows x 2 segs) = 8 cp/lane
__device__ __forceinline__ void load_warp(uint32_t stage_base, int i0r, int j0,
                                          size_t koff, int lane)
{
#pragma unroll
    for (int it = 0; it < 8; ++it) {
        int cid = it * 32 + lane;            // 0..255
        int buf = cid >> 6;                  // 0:AHI 1:ALO 2:BHI 3:BLO
        int rc  = cid & 63;
        int row = rc >> 1;
        int seg = rc & 1;
        uint32_t dst = stage_base + (uint32_t)(buf << 10) + swz32(row, seg);
        const int rowg = (buf < 2 ? i0r : j0) + row;
        const __nv_bfloat16* base = (buf & 1) ? g_lo : g_hi;
        cp16(dst, base + (size_t)rowg * N_PTS + koff + seg * 8);
    }
}

__global__ void __launch_bounds__(256, 2) syrk_mma_kernel(float* __restrict__ out)
{
    extern __shared__ __align__(1024) char smem[];
    const uint32_t sbase = smem_u32(smem);
    const int tid  = threadIdx.x;
    const int lane = tid & 31;
    const int wid  = tid >> 5;
    const int ms   = wid & 1;               // m-half (32 rows of 64)
    const int kset = wid >> 1;              // k-quarter (16 of 64 per chunk)
    const uint32_t wbase = sbase + (uint32_t)wid * WBUF;

    // decode tile: ti (64-row block, 0..15), tj (32-col block, 2*ti..31)
    int b = blockIdx.x, ti = 0, rem = b;
    while (rem >= 32 - 2 * ti) { rem -= 32 - 2 * ti; ++ti; }
    const int tj = 2 * ti + rem;
    const int i0 = ti * 64;
    const int j0 = tj * 32;
    const int i0r = i0 + ms * 32;
    const bool diagTile = ((tj >> 1) == ti);

    // ldmatrix addresses within the private buffer
    const int g  = lane >> 3;
    const int rr = lane & 7;
    uint32_t a_addr[2], b_addr[2];
#pragma unroll
    for (int mf = 0; mf < 2; ++mf) {
        int m   = mf * 16 + rr + (g & 1) * 8;
        a_addr[mf] = wbase + A_HI_OFF + swz32(m, g >> 1);
    }
#pragma unroll
    for (int nf2 = 0; nf2 < 2; ++nf2) {
        int n   = nf2 * 16 + rr + (g >> 1) * 8;
        b_addr[nf2] = wbase + B_HI_OFF + swz32(n, g & 1);
    }

    float acc[2][4][4];
#pragma unroll
    for (int mf = 0; mf < 2; ++mf)
#pragma unroll
        for (int nf = 0; nf < 4; ++nf)
#pragma unroll
            for (int r2 = 0; r2 < 4; ++r2) acc[mf][nf][r2] = 0.0f;

    const size_t kbase = (size_t)kset * 16;
    load_warp(wbase,          i0r, j0, kbase,      lane); cp_commit();
    load_warp(wbase + WSTAGE, i0r, j0, kbase + 64, lane); cp_commit();

    for (int sc = 0; sc < NSC; ++sc) {
        cp_wait<1>();                         // this warp's chunk sc complete
        const uint32_t so = (uint32_t)(sc & 1) * WSTAGE;

        uint32_t ah[2][4], al[2][4], bh[2][4], bl[2][4];
        ldsm4(ah[0], a_addr[0] + so);
        ldsm4(ah[1], a_addr[1] + so);
        ldsm4(al[0], a_addr[0] + so + (A_LO_OFF - A_HI_OFF));
        ldsm4(al[1], a_addr[1] + so + (A_LO_OFF - A_HI_OFF));
        ldsm4(bh[0], b_addr[0] + so);
        ldsm4(bh[1], b_addr[1] + so);
        ldsm4(bl[0], b_addr[0] + so + (B_LO_OFF - B_HI_OFF));
        ldsm4(bl[1], b_addr[1] + so + (B_LO_OFF - B_HI_OFF));

        // hh chain
#pragma unroll
        for (int mf = 0; mf < 2; ++mf)
#pragma unroll
            for (int nf = 0; nf < 4; ++nf)
                mma_bf16(acc[mf][nf], ah[mf],
                         bh[nf >> 1][(nf & 1) * 2], bh[nf >> 1][(nf & 1) * 2 + 1]);

        // refill this stage for chunk sc+2 (all stage ldsm issued above)
        if (sc + 2 < NSC)
            load_warp(wbase + so, i0r, j0,
                      kbase + (size_t)(sc + 2) * 64, lane);
        cp_commit();

        // hl chain
#pragma unroll
        for (int mf = 0; mf < 2; ++mf)
#pragma unroll
            for (int nf = 0; nf < 4; ++nf)
                mma_bf16(acc[mf][nf], ah[mf],
                         bl[nf >> 1][(nf & 1) * 2], bl[nf >> 1][(nf & 1) * 2 + 1]);
        // lh chain
#pragma unroll
        for (int mf = 0; mf < 2; ++mf)
#pragma unroll
            for (int nf = 0; nf < 4; ++nf)
                mma_bf16(acc[mf][nf], al[mf],
                         bh[nf >> 1][(nf & 1) * 2], bh[nf >> 1][(nf & 1) * 2 + 1]);
    }

    // ---- epilogue: 4-set reduction + write (tile, mirror, diag) ----
    __syncthreads();                          // all warps done with private bufs
    const int r0   = lane >> 2;
    const int cpos = (lane & 3) * 2;
    float* sdiag8 = (float*)(smem + SDIAG_OFF);   // [8][32]

    if (diagTile) {                           // per-column partial sums
        const int c  = tid & 31;
        const int gq = tid >> 5;              // 0..7
        float s = 0.0f;
#pragma unroll 8
        for (int p = gq * 32; p < gq * 32 + 32; ++p)
            s += g_dpart[p * KQ + j0 + c];
        sdiag8[gq * 32 + c] = s;
    }

    if (kset >= 1) {                          // stash to [kset-1][ms] buffer
        float (*red)[33] =
            (float (*)[33])(smem + (size_t)((kset - 1) * 2 + ms) * RED_SET);
#pragma unroll
        for (int mf = 0; mf < 2; ++mf)
#pragma unroll
            for (int nf = 0; nf < 4; ++nf) {
                const int rl = mf * 16 + r0;
                const int cl = nf * 8 + cpos;
                red[rl][cl]         = acc[mf][nf][0];
                red[rl][cl + 1]     = acc[mf][nf][1];
                red[rl + 8][cl]     = acc[mf][nf][2];
                red[rl + 8][cl + 1] = acc[mf][nf][3];
            }
    }
    __syncthreads();

    if (kset == 0) {
        float* __restrict__ G = out + EPHI_SZ;
        float (*red0)[33] = (float (*)[33])(smem + (size_t)(0 * 2 + ms) * RED_SET);
        float (*red1)[33] = (float (*)[33])(smem + (size_t)(1 * 2 + ms) * RED_SET);
        float (*red2)[33] = (float (*)[33])(smem + (size_t)(2 * 2 + ms) * RED_SET);
#pragma unroll
        for (int mf = 0; mf < 2; ++mf)
#pragma unroll
            for (int nf = 0; nf < 4; ++nf)
#pragma unroll
                for (int r2 = 0; r2 < 4; ++r2) {
                    const int rl = mf * 16 + r0 + (r2 >> 1) * 8;
                    const int cl = nf * 8 + cpos + (r2 & 1);
                    const int gi = i0 + ms * 32 + rl;
                    const int gj = j0 + cl;
                    float val = acc[mf][nf][r2]
                              + red0[rl][cl] + red1[rl][cl] + red2[rl][cl];
                    if (diagTile && gi == gj) {
                        float dv = 0.0f;
#pragma unroll
                        for (int gq = 0; gq < 8; ++gq)
                            dv += sdiag8[gq * 32 + cl];
                        val = dv;
                    }
                    G[(size_t)gi * KQ + gj] = val;
                    G[(size_t)gj * KQ + gi] = val;
                }
    }
}

// ---------------------------------------------------------------------------
extern "C" void kernel_launch(void* const* d_in, const int* in_sizes, int n_in,
                              void* d_out, int out_size)
{
    const float* X           = (const float*)d_in[0];
    const float* z           = (const float*)d_in[1];
    const float* weight      = (const float*)d_in[2];
    const float* mu          = (const float*)d_in[3];
    const float* stdv        = (const float*)d_in[4];
    const float* alpha       = (const float*)d_in[5];
    const float* var_mu_w    = (const float*)d_in[6];
    const float* var_sigma_w = (const float*)d_in[7];
    float* out = (float*)d_out;

    cudaFuncSetAttribute(syrk_mma_kernel,
                         cudaFuncAttributeMaxDynamicSharedMemorySize, SMEM_SYRK);

    dim3 egrid(KQ / 256, N_PTS / 32);
    ephi_kernel<<<egrid, 256>>>(X, z, weight, mu, stdv, alpha,
                                var_mu_w, var_sigma_w, out);

    syrk_mma_kernel<<<272, 256, SMEM_SYRK>>>(out);
}

// round 14
// speedup vs baseline: 1.7242x; 1.7242x over previous
#include <cuda_runtime.h>
#include <cuda_bf16.h>
#include <math.h>
#include <stdint.h>

#define N_PTS   8192
#define D_DIM   8
#define K_DIM   64
#define Q_DIM   16
#define KQ      1024
#define TWO_PI  6.283185307179586f

#define EPHI_SZ (N_PTS * KQ)    // 8388608
#define G_SZ    (KQ * KQ)       // 1048576
// d_out layout: [E_phi (N,KQ) | G (KQ,KQ) | E_cos_sq (N,KQ)]

// -------- device scratch --------
__device__ float g_dpart[256 * KQ];
__device__ float g_diag[KQ];
__device__ __nv_bfloat16 g_hi[(size_t)KQ * N_PTS];
__device__ __nv_bfloat16 g_lo[(size_t)KQ * N_PTS];

// ---------------------------------------------------------------------------
// helpers
// ---------------------------------------------------------------------------
__device__ __forceinline__ uint32_t smem_u32(const void* p) {
    uint32_t a;
    asm("{ .reg .u64 t; cvta.to.shared.u64 t, %1; cvt.u32.u64 %0, t; }"
        : "=r"(a) : "l"(p));
    return a;
}
__device__ __forceinline__ void cp16(uint32_t dst, const void* src) {
    asm volatile("cp.async.cg.shared.global [%0], [%1], 16;"
                 :: "r"(dst), "l"(src));
}
__device__ __forceinline__ void cp_commit() {
    asm volatile("cp.async.commit_group;" ::: "memory");
}
template <int N>
__device__ __forceinline__ void cp_wait() {
    asm volatile("cp.async.wait_group %0;" :: "n"(N) : "memory");
}
__device__ __forceinline__ void ldsm4(uint32_t* r, uint32_t addr) {
    asm volatile("ldmatrix.sync.aligned.m8n8.x4.shared.b16 {%0,%1,%2,%3}, [%4];"
                 : "=r"(r[0]), "=r"(r[1]), "=r"(r[2]), "=r"(r[3]) : "r"(addr));
}
__device__ __forceinline__ void mma_bf16(float* c, const uint32_t* a,
                                         uint32_t b0, uint32_t b1) {
    asm volatile(
        "mma.sync.aligned.m16n8k16.row.col.f32.bf16.bf16.f32 "
        "{%0,%1,%2,%3}, {%4,%5,%6,%7}, {%8,%9}, {%0,%1,%2,%3};"
        : "+f"(c[0]), "+f"(c[1]), "+f"(c[2]), "+f"(c[3])
        : "r"(a[0]), "r"(a[1]), "r"(a[2]), "r"(a[3]), "r"(b0), "r"(b1));
}

// swizzled offset within a 64B-row warp-private buffer (16B granules)
__device__ __forceinline__ uint32_t swz(int row, int seg) {
    return (uint32_t)(row * 64 + ((seg ^ ((row >> 1) & 3)) << 4));
}

// ---------------------------------------------------------------------------
// Kernel 1: fused E_phi, E_cos_sq, split-bf16 transposed hi/lo, diag partials.
// Coefficient tables computed per-block in smem. (R12-proven, ~21us)
// ---------------------------------------------------------------------------
__global__ void __launch_bounds__(256) ephi_kernel(const float* __restrict__ X,
                            const float* __restrict__ z,
                            const float* __restrict__ weight,
                            const float* __restrict__ mu,
                            const float* __restrict__ stdv,
                            const float* __restrict__ alpha,
                            const float* __restrict__ var_mu_w,
                            const float* __restrict__ var_sigma_w,
                            float* __restrict__ out)
{
    const int tid = threadIdx.x;
    const int kq0 = blockIdx.x * 256;
    const int kq  = kq0 + tid;
    const int n0  = blockIdx.y * 32;

    __shared__ float Xs[256];
    __shared__ float s_mp[128], s_sp[128];     // mean_p, std_p per (d,q)
    __shared__ __nv_bfloat16 s_hi[256][34];
    __shared__ __nv_bfloat16 s_lo[256][34];

    Xs[tid] = TWO_PI * X[n0 * D_DIM + tid];
    if (tid < 128) {
        s_mp[tid] = 1.0f / (mu[tid] + 1e-8f);
        s_sp[tid] = 1.0f / (TWO_PI * stdv[tid] + 1e-8f);
    }
    __syncthreads();

    const int q = kq & (Q_DIM - 1);
    float ew[D_DIM], cc[D_DIM], zz[D_DIM];
#pragma unroll
    for (int d = 0; d < D_DIM; ++d) {
        const float mp = s_mp[d * Q_DIM + q];
        const float sp = s_sp[d * Q_DIM + q];
        ew[d] = mp + sp * var_mu_w[d * KQ + kq];
        cc[d] = sp * sp * var_sigma_w[d * KQ + kq];
        zz[d] = TWO_PI * z[d * KQ + kq];
    }
    const float a    = alpha[kq];
    const float coef = 2.0f * weight[q] * (1.0f / (float)K_DIM);
    const float sq   = sqrtf(coef);

    float* __restrict__ outE = out;
    float* __restrict__ outC = out + EPHI_SZ + G_SZ;

    float dsum = 0.0f;
#pragma unroll 4
    for (int r = 0; r < 32; ++r) {
        float phase = 0.0f, s = 0.0f;
#pragma unroll
        for (int d = 0; d < D_DIM; ++d) {
            float xb = Xs[r * D_DIM + d] - zz[d];
            phase = fmaf(xb, ew[d], phase);
            s     = fmaf(cc[d], xb * xb, s);
        }
        float cw    = __cosf(a + phase);
        float decay = __expf(-0.5f * s);

        const int n = n0 + r;
        float E = sq * decay * cw;
        outE[n * KQ + kq] = E;

        float d2  = decay * decay;
        float d4  = d2 * d2;
        float c2w = 2.0f * cw * cw - 1.0f;
        float ecs = coef * (0.5f + 0.5f * d4 * c2w);
        outC[n * KQ + kq] = ecs;
        dsum += ecs;

        __nv_bfloat16 h = __float2bfloat16(E);
        s_hi[tid][r] = h;
        s_lo[tid][r] = __float2bfloat16(E - __bfloat162float(h));
    }
    g_dpart[blockIdx.y * KQ + kq] = dsum;
    __syncthreads();

    uint32_t* __restrict__ H = (uint32_t*)g_hi;
    uint32_t* __restrict__ L = (uint32_t*)g_lo;
#pragma unroll
    for (int i = 0; i < 16; ++i) {
        int v   = tid + i * 256;
        int row = v >> 4;
        int seg = v & 15;
        uint32_t h2 = *(const uint32_t*)&s_hi[row][seg * 2];
        uint32_t l2 = *(const uint32_t*)&s_lo[row][seg * 2];
        size_t o = ((size_t)(kq0 + row) * N_PTS + n0) / 2 + seg;
        H[o] = h2;
        L[o] = l2;
    }
}

// ---------------------------------------------------------------------------
// Kernel 2: reduce diag partials (256 partials per kq) — external, ~2.5us
// ---------------------------------------------------------------------------
__global__ void diag_reduce_kernel()
{
    int kq = blockIdx.x * 256 + threadIdx.x;
    float s = 0.0f;
    for (int p = 0; p < 256; ++p)
        s += g_dpart[p * KQ + kq];
    g_diag[kq] = s;
}

// ---------------------------------------------------------------------------
// Kernel 3: SYRK — EXACT R8 kernel (proven 71.0us / tensor 63%).
// Warp-autonomous pipelines, no mainloop __syncthreads.
// 136 upper-triangular 64x64 tiles, 256 threads = 8 warps.
// Warp (ms, kset): ms = m-half (32 rows), kset = k-quarter (32 of 128 per sc).
// Warp-private smem: stage = AHI 2KB | ALO 2KB | BHI 4KB | BLO 4KB = 12KB,
// double buffered -> 24KB/warp, 192KB/CTA.
// Epilogue: 4-set smem reduce + write/mirror + g_diag splice.
// ---------------------------------------------------------------------------
#define A_HI_OFF 0
#define A_LO_OFF 2048
#define B_HI_OFF 4096
#define B_LO_OFF 8192
#define WSTAGE   12288
#define WBUF     (2 * WSTAGE)        // 24576 per warp
#define SMEM_SYRK (8 * WBUF)         // 196608
#define NSC 64
#define RED_STRIDE 65
#define RED_BYTES (64 * RED_STRIDE * 4)   // 16640

__device__ __forceinline__ void load_warp(uint32_t stage_base, int i0r, int j0,
                                          size_t koff, int lane)
{
    // A: 32 rows x 32k, hi+lo = 256 16B-chunks; B: 64 rows x 32k = 512 chunks
#pragma unroll
    for (int it = 0; it < 8; ++it) {
        int cid = it * 32 + lane;
        int h   = cid >> 7;
        int rc  = cid & 127;
        int row = rc >> 2;
        int seg = rc & 3;
        uint32_t dst = stage_base + (uint32_t)(h ? A_LO_OFF : A_HI_OFF) + swz(row, seg);
        const __nv_bfloat16* base = h ? g_lo : g_hi;
        cp16(dst, (const char*)(base + (size_t)(i0r + row) * N_PTS + koff) + seg * 16);
    }
#pragma unroll
    for (int it = 0; it < 16; ++it) {
        int cid = it * 32 + lane;
        int h   = cid >> 8;
        int rc  = cid & 255;
        int row = rc >> 2;
        int seg = rc & 3;
        uint32_t dst = stage_base + (uint32_t)(h ? B_LO_OFF : B_HI_OFF) + swz(row, seg);
        const __nv_bfloat16* base = h ? g_lo : g_hi;
        cp16(dst, (const char*)(base + (size_t)(j0 + row) * N_PTS + koff) + seg * 16);
    }
}

__global__ void __launch_bounds__(256, 1) syrk_mma_kernel(float* __restrict__ out)
{
    extern __shared__ __align__(1024) char smem[];
    const uint32_t sbase = smem_u32(smem);
    const int tid  = threadIdx.x;
    const int lane = tid & 31;
    const int wid  = tid >> 5;
    const int ms   = wid & 1;               // m-half
    const int kset = wid >> 1;              // k-quarter
    const int wm   = ms * 32;
    const uint32_t wbase = sbase + (uint32_t)wid * WBUF;

    int b = blockIdx.x, ti = 0, rem = b;
    while (rem >= 16 - ti) { rem -= 16 - ti; ++ti; }
    const int tj = ti + rem;
    const int i0 = ti * 64;
    const int j0 = tj * 64;
    const int i0r = i0 + wm;

    // ldmatrix addresses within the private buffer
    const int g  = lane >> 3;
    const int rr = lane & 7;
    uint32_t a_addr[2][2], b_addr[4][2];
#pragma unroll
    for (int mf = 0; mf < 2; ++mf)
#pragma unroll
        for (int ks = 0; ks < 2; ++ks) {
            int m   = mf * 16 + rr + (g & 1) * 8;
            int seg = (g >> 1) + ks * 2;
            a_addr[mf][ks] = wbase + A_HI_OFF + swz(m, seg);
        }
#pragma unroll
    for (int nf2 = 0; nf2 < 4; ++nf2)
#pragma unroll
        for (int ks = 0; ks < 2; ++ks) {
            int n   = nf2 * 16 + rr + (g >> 1) * 8;
            int seg = (g & 1) + ks * 2;
            b_addr[nf2][ks] = wbase + B_HI_OFF + swz(n, seg);
        }

    float acc[2][8][4];
#pragma unroll
    for (int mf = 0; mf < 2; ++mf)
#pragma unroll
        for (int nf = 0; nf < 8; ++nf)
#pragma unroll
            for (int r2 = 0; r2 < 4; ++r2) acc[mf][nf][r2] = 0.0f;

    const size_t kbase = (size_t)kset * 32;
    load_warp(wbase,          i0r, j0, kbase,       lane); cp_commit();
    load_warp(wbase + WSTAGE, i0r, j0, kbase + 128, lane); cp_commit();

    for (int sc = 0; sc < NSC; ++sc) {
        cp_wait<1>();                         // this warp's chunk sc complete
        const uint32_t so = (uint32_t)(sc & 1) * WSTAGE;

#pragma unroll
        for (int ks = 0; ks < 2; ++ks) {
            uint32_t ah[2][4], al[2][4], bh[4][4], bl[4][4];
            ldsm4(ah[0], a_addr[0][ks] + so);
            ldsm4(ah[1], a_addr[1][ks] + so);
            ldsm4(al[0], a_addr[0][ks] + so + (A_LO_OFF - A_HI_OFF));
            ldsm4(al[1], a_addr[1][ks] + so + (A_LO_OFF - A_HI_OFF));
#pragma unroll
            for (int nf2 = 0; nf2 < 4; ++nf2) {
                ldsm4(bh[nf2], b_addr[nf2][ks] + so);
                ldsm4(bl[nf2], b_addr[nf2][ks] + so + (B_LO_OFF - B_HI_OFF));
            }

            // hh chain
#pragma unroll
            for (int mf = 0; mf < 2; ++mf)
#pragma unroll
                for (int nf = 0; nf < 8; ++nf)
                    mma_bf16(acc[mf][nf], ah[mf],
                             bh[nf >> 1][(nf & 1) * 2], bh[nf >> 1][(nf & 1) * 2 + 1]);

            // refill: after ALL ldsm of this stage (ks==1 only), single commit
            if (ks == 1) {
                if (sc + 2 < NSC)
                    load_warp(wbase + so, i0r, j0,
                              kbase + (size_t)(sc + 2) * 128, lane);
                cp_commit();
            }

            // hl chain
#pragma unroll
            for (int mf = 0; mf < 2; ++mf)
#pragma unroll
                for (int nf = 0; nf < 8; ++nf)
                    mma_bf16(acc[mf][nf], ah[mf],
                             bl[nf >> 1][(nf & 1) * 2], bl[nf >> 1][(nf & 1) * 2 + 1]);
            // lh chain
#pragma unroll
            for (int mf = 0; mf < 2; ++mf)
#pragma unroll
                for (int nf = 0; nf < 8; ++nf)
                    mma_bf16(acc[mf][nf], al[mf],
                             bh[nf >> 1][(nf & 1) * 2], bh[nf >> 1][(nf & 1) * 2 + 1]);
        }
    }

    // ---- epilogue: 4-set reduction + write (tile, mirror, diag splice) ----
    __syncthreads();                          // all warps done with private bufs
    const int r0   = lane >> 2;
    const int cpos = (lane & 3) * 2;

    if (kset >= 1) {
        float (*red)[RED_STRIDE] =
            (float (*)[RED_STRIDE])(smem + (size_t)(kset - 1) * RED_BYTES);
#pragma unroll
        for (int mf = 0; mf < 2; ++mf)
#pragma unroll
            for (int nf = 0; nf < 8; ++nf) {
                const int rl = wm + mf * 16 + r0;
                const int cl = nf * 8 + cpos;
                red[rl][cl]         = acc[mf][nf][0];
                red[rl][cl + 1]     = acc[mf][nf][1];
                red[rl + 8][cl]     = acc[mf][nf][2];
                red[rl + 8][cl + 1] = acc[mf][nf][3];
            }
    }
    __syncthreads();

    if (kset == 0) {
        float* __restrict__ G = out + EPHI_SZ;
        float (*red0)[RED_STRIDE] = (float (*)[RED_STRIDE])(smem);
        float (*red1)[RED_STRIDE] = (float (*)[RED_STRIDE])(smem + RED_BYTES);
        float (*red2)[RED_STRIDE] = (float (*)[RED_STRIDE])(smem + 2 * RED_BYTES);
#pragma unroll
        for (int mf = 0; mf < 2; ++mf)
#pragma unroll
            for (int nf = 0; nf < 8; ++nf)
#pragma unroll
                for (int r2 = 0; r2 < 4; ++r2) {
                    const int rl = wm + mf * 16 + r0 + (r2 >> 1) * 8;
                    const int cl = nf * 8 + cpos + (r2 & 1);
                    const int gi = i0 + rl;
                    const int gj = j0 + cl;
                    float val = acc[mf][nf][r2]
                              + red0[rl][cl] + red1[rl][cl] + red2[rl][cl];
                    if (gi == gj) val = g_diag[gi];
                    G[(size_t)gi * KQ + gj] = val;
                    G[(size_t)gj * KQ + gi] = val;
                }
    }
}

// ---------------------------------------------------------------------------
extern "C" void kernel_launch(void* const* d_in, const int* in_sizes, int n_in,
                              void* d_out, int out_size)
{
    const float* X           = (const float*)d_in[0];
    const float* z           = (const float*)d_in[1];
    const float* weight      = (const float*)d_in[2];
    const float* mu          = (const float*)d_in[3];
    const float* stdv        = (const float*)d_in[4];
    const float* alpha       = (const float*)d_in[5];
    const float* var_mu_w    = (const float*)d_in[6];
    const float* var_sigma_w = (const float*)d_in[7];
    float* out = (float*)d_out;

    cudaFuncSetAttribute(syrk_mma_kernel,
                         cudaFuncAttributeMaxDynamicSharedMemorySize, SMEM_SYRK);

    dim3 egrid(KQ / 256, N_PTS / 32);
    ephi_kernel<<<egrid, 256>>>(X, z, weight, mu, stdv, alpha,
                                var_mu_w, var_sigma_w, out);

    diag_reduce_kernel<<<4, 256>>>();

    syrk_mma_kernel<<<136, 256, SMEM_SYRK>>>(out);
}

// round 15
// speedup vs baseline: 1.7369x; 1.0073x over previous
#include <cuda_runtime.h>
#include <cuda_bf16.h>
#include <math.h>
#include <stdint.h>

#define N_PTS   8192
#define D_DIM   8
#define K_DIM   64
#define Q_DIM   16
#define KQ      1024
#define TWO_PI  6.283185307179586f

#define EPHI_SZ (N_PTS * KQ)    // 8388608
#define G_SZ    (KQ * KQ)       // 1048576
// d_out layout: [E_phi (N,KQ) | G (KQ,KQ) | E_cos_sq (N,KQ)]

// -------- device scratch --------
__device__ float g_dpart[256 * KQ];
__device__ float g_diag[KQ];
__device__ __nv_bfloat16 g_hi[(size_t)KQ * N_PTS];
__device__ __nv_bfloat16 g_lo[(size_t)KQ * N_PTS];

// ---------------------------------------------------------------------------
// helpers
// ---------------------------------------------------------------------------
__device__ __forceinline__ uint32_t smem_u32(const void* p) {
    uint32_t a;
    asm("{ .reg .u64 t; cvta.to.shared.u64 t, %1; cvt.u32.u64 %0, t; }"
        : "=r"(a) : "l"(p));
    return a;
}
__device__ __forceinline__ void cp16(uint32_t dst, const void* src) {
    asm volatile("cp.async.cg.shared.global [%0], [%1], 16;"
                 :: "r"(dst), "l"(src));
}
__device__ __forceinline__ void cp_commit() {
    asm volatile("cp.async.commit_group;" ::: "memory");
}
template <int N>
__device__ __forceinline__ void cp_wait() {
    asm volatile("cp.async.wait_group %0;" :: "n"(N) : "memory");
}
__device__ __forceinline__ void bar_sync(int id, int cnt) {
    asm volatile("bar.sync %0, %1;" :: "r"(id), "r"(cnt) : "memory");
}
__device__ __forceinline__ void ldsm4(uint32_t* r, uint32_t addr) {
    asm volatile("ldmatrix.sync.aligned.m8n8.x4.shared.b16 {%0,%1,%2,%3}, [%4];"
                 : "=r"(r[0]), "=r"(r[1]), "=r"(r[2]), "=r"(r[3]) : "r"(addr));
}
__device__ __forceinline__ void mma_bf16(float* c, const uint32_t* a,
                                         uint32_t b0, uint32_t b1) {
    asm volatile(
        "mma.sync.aligned.m16n8k16.row.col.f32.bf16.bf16.f32 "
        "{%0,%1,%2,%3}, {%4,%5,%6,%7}, {%8,%9}, {%0,%1,%2,%3};"
        : "+f"(c[0]), "+f"(c[1]), "+f"(c[2]), "+f"(c[3])
        : "r"(a[0]), "r"(a[1]), "r"(a[2]), "r"(a[3]), "r"(b0), "r"(b1));
}

// swizzled offset within a 64B-row buffer (16B granules)
__device__ __forceinline__ uint32_t swz(int row, int seg) {
    return (uint32_t)(row * 64 + ((seg ^ ((row >> 1) & 3)) << 4));
}

// ---------------------------------------------------------------------------
// Kernel 1: fused E_phi, E_cos_sq, split-bf16 transposed hi/lo, diag partials.
// (R12/R14-proven)
// ---------------------------------------------------------------------------
__global__ void __launch_bounds__(256) ephi_kernel(const float* __restrict__ X,
                            const float* __restrict__ z,
                            const float* __restrict__ weight,
                            const float* __restrict__ mu,
                            const float* __restrict__ stdv,
                            const float* __restrict__ alpha,
                            const float* __restrict__ var_mu_w,
                            const float* __restrict__ var_sigma_w,
                            float* __restrict__ out)
{
    const int tid = threadIdx.x;
    const int kq0 = blockIdx.x * 256;
    const int kq  = kq0 + tid;
    const int n0  = blockIdx.y * 32;

    __shared__ float Xs[256];
    __shared__ float s_mp[128], s_sp[128];
    __shared__ __nv_bfloat16 s_hi[256][34];
    __shared__ __nv_bfloat16 s_lo[256][34];

    Xs[tid] = TWO_PI * X[n0 * D_DIM + tid];
    if (tid < 128) {
        s_mp[tid] = 1.0f / (mu[tid] + 1e-8f);
        s_sp[tid] = 1.0f / (TWO_PI * stdv[tid] + 1e-8f);
    }
    __syncthreads();

    const int q = kq & (Q_DIM - 1);
    float ew[D_DIM], cc[D_DIM], zz[D_DIM];
#pragma unroll
    for (int d = 0; d < D_DIM; ++d) {
        const float mp = s_mp[d * Q_DIM + q];
        const float sp = s_sp[d * Q_DIM + q];
        ew[d] = mp + sp * var_mu_w[d * KQ + kq];
        cc[d] = sp * sp * var_sigma_w[d * KQ + kq];
        zz[d] = TWO_PI * z[d * KQ + kq];
    }
    const float a    = alpha[kq];
    const float coef = 2.0f * weight[q] * (1.0f / (float)K_DIM);
    const float sq   = sqrtf(coef);

    float* __restrict__ outE = out;
    float* __restrict__ outC = out + EPHI_SZ + G_SZ;

    float dsum = 0.0f;
#pragma unroll 4
    for (int r = 0; r < 32; ++r) {
        float phase = 0.0f, s = 0.0f;
#pragma unroll
        for (int d = 0; d < D_DIM; ++d) {
            float xb = Xs[r * D_DIM + d] - zz[d];
            phase = fmaf(xb, ew[d], phase);
            s     = fmaf(cc[d], xb * xb, s);
        }
        float cw    = __cosf(a + phase);
        float decay = __expf(-0.5f * s);

        const int n = n0 + r;
        float E = sq * decay * cw;
        outE[n * KQ + kq] = E;

        float d2  = decay * decay;
        float d4  = d2 * d2;
        float c2w = 2.0f * cw * cw - 1.0f;
        float ecs = coef * (0.5f + 0.5f * d4 * c2w);
        outC[n * KQ + kq] = ecs;
        dsum += ecs;

        __nv_bfloat16 h = __float2bfloat16(E);
        s_hi[tid][r] = h;
        s_lo[tid][r] = __float2bfloat16(E - __bfloat162float(h));
    }
    g_dpart[blockIdx.y * KQ + kq] = dsum;
    __syncthreads();

    uint32_t* __restrict__ H = (uint32_t*)g_hi;
    uint32_t* __restrict__ L = (uint32_t*)g_lo;
#pragma unroll
    for (int i = 0; i < 16; ++i) {
        int v   = tid + i * 256;
        int row = v >> 4;
        int seg = v & 15;
        uint32_t h2 = *(const uint32_t*)&s_hi[row][seg * 2];
        uint32_t l2 = *(const uint32_t*)&s_lo[row][seg * 2];
        size_t o = ((size_t)(kq0 + row) * N_PTS + n0) / 2 + seg;
        H[o] = h2;
        L[o] = l2;
    }
}

// ---------------------------------------------------------------------------
// Kernel 2: reduce diag partials
// ---------------------------------------------------------------------------
__global__ void diag_reduce_kernel()
{
    int kq = blockIdx.x * 256 + threadIdx.x;
    float s = 0.0f;
    for (int p = 0; p < 256; ++p)
        s += g_dpart[p * KQ + kq];
    g_diag[kq] = s;
}

// ---------------------------------------------------------------------------
// Kernel 3: SYRK — R8 schedule + PAIR-SHARED B buffers.
// 136 upper-triangular 64x64 tiles, 256 threads = 8 warps.
// Warp (ms, kset): ms = m-half (32 rows), kset = k-quarter (32 of 128 per sc).
// A: warp-private, stage = AHI 2KB | ALO 2KB, x2 stages = 8KB/warp (64KB).
// B: SHARED per kset pair, stage = BHI 4KB | BLO 4KB, x2 stages = 16KB/kset
//    (64KB). Each pair-warp loads its 32-row half of B.
// Per sc: cp_wait<1>; bar.sync(1+kset,64) [partner's half visible]; batched
// ldsm; bar.sync(1+kset,64) [stage reads done]; hh chain; refill (A+B-half,
// single commit); hl chain; lh chain. Total smem 128KB.
// Epilogue: 4-set smem reduce + write/mirror + g_diag splice.
// ---------------------------------------------------------------------------
#define A_STAGE  4096                 // AHI 2048 | ALO 2048
#define A_WBUF   (2 * A_STAGE)        // 8192 per warp
#define B_REGION (8 * A_WBUF)         // 65536: B region base
#define B_STAGE  8192                 // BHI 4096 | BLO 4096
#define B_KBUF   (2 * B_STAGE)        // 16384 per kset
#define SMEM_SYRK (B_REGION + 4 * B_KBUF)   // 131072
#define NSC 64
#define RED_STRIDE 65
#define RED_BYTES (64 * RED_STRIDE * 4)   // 16640

// A refill: 32 rows x 32k, hi+lo = 256 16B-chunks (8 cp per lane)
__device__ __forceinline__ void load_A(uint32_t astage, int i0r,
                                       size_t koff, int lane)
{
#pragma unroll
    for (int it = 0; it < 8; ++it) {
        int cid = it * 32 + lane;
        int h   = cid >> 7;
        int rc  = cid & 127;
        int row = rc >> 2;
        int seg = rc & 3;
        uint32_t dst = astage + (uint32_t)(h ? 2048 : 0) + swz(row, seg);
        const __nv_bfloat16* base = h ? g_lo : g_hi;
        cp16(dst, (const char*)(base + (size_t)(i0r + row) * N_PTS + koff) + seg * 16);
    }
}
// B-half refill: 32 rows (ms half) x 32k, hi+lo = 256 chunks (8 cp per lane)
__device__ __forceinline__ void load_Bhalf(uint32_t bstage, int j0, int ms,
                                           size_t koff, int lane)
{
#pragma unroll
    for (int it = 0; it < 8; ++it) {
        int cid = it * 32 + lane;
        int h   = cid >> 7;
        int rc  = cid & 127;
        int row = (rc >> 2) + ms * 32;       // rows ms*32 .. ms*32+31
        int seg = rc & 3;
        uint32_t dst = bstage + (uint32_t)(h ? 4096 : 0) + swz(row, seg);
        const __nv_bfloat16* base = h ? g_lo : g_hi;
        cp16(dst, (const char*)(base + (size_t)(j0 + row) * N_PTS + koff) + seg * 16);
    }
}

__global__ void __launch_bounds__(256, 1) syrk_mma_kernel(float* __restrict__ out)
{
    extern __shared__ __align__(1024) char smem[];
    const uint32_t sbase = smem_u32(smem);
    const int tid  = threadIdx.x;
    const int lane = tid & 31;
    const int wid  = tid >> 5;
    const int ms   = wid & 1;               // m-half
    const int kset = wid >> 1;              // k-quarter
    const int wm   = ms * 32;
    const int barid = 1 + kset;             // named barrier per pair
    const uint32_t abase = sbase + (uint32_t)wid * A_WBUF;
    const uint32_t bbase = sbase + B_REGION + (uint32_t)kset * B_KBUF;

    int b = blockIdx.x, ti = 0, rem = b;
    while (rem >= 16 - ti) { rem -= 16 - ti; ++ti; }
    const int tj = ti + rem;
    const int i0 = ti * 64;
    const int j0 = tj * 64;
    const int i0r = i0 + wm;

    // ldmatrix addresses
    const int g  = lane >> 3;
    const int rr = lane & 7;
    uint32_t a_addr[2][2], b_addr[4][2];
#pragma unroll
    for (int mf = 0; mf < 2; ++mf)
#pragma unroll
        for (int ks = 0; ks < 2; ++ks) {
            int m   = mf * 16 + rr + (g & 1) * 8;
            int seg = (g >> 1) + ks * 2;
            a_addr[mf][ks] = abase + swz(m, seg);              // AHI
        }
#pragma unroll
    for (int nf2 = 0; nf2 < 4; ++nf2)
#pragma unroll
        for (int ks = 0; ks < 2; ++ks) {
            int n   = nf2 * 16 + rr + (g >> 1) * 8;
            int seg = (g & 1) + ks * 2;
            b_addr[nf2][ks] = bbase + swz(n, seg);             // BHI
        }

    float acc[2][8][4];
#pragma unroll
    for (int mf = 0; mf < 2; ++mf)
#pragma unroll
        for (int nf = 0; nf < 8; ++nf)
#pragma unroll
            for (int r2 = 0; r2 < 4; ++r2) acc[mf][nf][r2] = 0.0f;

    const size_t kbase = (size_t)kset * 32;
    load_A(abase,           i0r,     kbase,       lane);
    load_Bhalf(bbase,       j0, ms,  kbase,       lane);
    cp_commit();
    load_A(abase + A_STAGE, i0r,     kbase + 128, lane);
    load_Bhalf(bbase + B_STAGE, j0, ms, kbase + 128, lane);
    cp_commit();

    for (int sc = 0; sc < NSC; ++sc) {
        cp_wait<1>();                         // own half of chunk sc complete
        bar_sync(barid, 64);                  // partner's half visible too
        const uint32_t soA = (uint32_t)(sc & 1) * A_STAGE;
        const uint32_t soB = (uint32_t)(sc & 1) * B_STAGE;

        // batched ldsm (R8-proven order), both ks
        uint32_t ah[2][2][4], al[2][2][4], bh[2][4][4], bl[2][4][4];
#pragma unroll
        for (int ks = 0; ks < 2; ++ks) {
            ldsm4(ah[ks][0], a_addr[0][ks] + soA);
            ldsm4(ah[ks][1], a_addr[1][ks] + soA);
            ldsm4(al[ks][0], a_addr[0][ks] + soA + 2048);
            ldsm4(al[ks][1], a_addr[1][ks] + soA + 2048);
#pragma unroll
            for (int nf2 = 0; nf2 < 4; ++nf2) {
                ldsm4(bh[ks][nf2], b_addr[nf2][ks] + soB);
                ldsm4(bl[ks][nf2], b_addr[nf2][ks] + soB + 4096);
            }
        }
        bar_sync(barid, 64);                  // pair done reading this stage

        // refill this stage for chunk sc+2 (own halves), single commit
        if (sc + 2 < NSC) {
            const size_t knext = kbase + (size_t)(sc + 2) * 128;
            load_A(abase + soA, i0r, knext, lane);
            load_Bhalf(bbase + soB, j0, ms, knext, lane);
        }
        cp_commit();

#pragma unroll
        for (int ks = 0; ks < 2; ++ks) {
            // hh chain
#pragma unroll
            for (int mf = 0; mf < 2; ++mf)
#pragma unroll
                for (int nf = 0; nf < 8; ++nf)
                    mma_bf16(acc[mf][nf], ah[ks][mf],
                             bh[ks][nf >> 1][(nf & 1) * 2],
                             bh[ks][nf >> 1][(nf & 1) * 2 + 1]);
            // hl chain
#pragma unroll
            for (int mf = 0; mf < 2; ++mf)
#pragma unroll
                for (int nf = 0; nf < 8; ++nf)
                    mma_bf16(acc[mf][nf], ah[ks][mf],
                             bl[ks][nf >> 1][(nf & 1) * 2],
                             bl[ks][nf >> 1][(nf & 1) * 2 + 1]);
            // lh chain
#pragma unroll
            for (int mf = 0; mf < 2; ++mf)
#pragma unroll
                for (int nf = 0; nf < 8; ++nf)
                    mma_bf16(acc[mf][nf], al[ks][mf],
                             bh[ks][nf >> 1][(nf & 1) * 2],
                             bh[ks][nf >> 1][(nf & 1) * 2 + 1]);
        }
    }

    // ---- epilogue: 4-set reduction + write (tile, mirror, diag splice) ----
    __syncthreads();
    const int r0   = lane >> 2;
    const int cpos = (lane & 3) * 2;

    if (kset >= 1) {
        float (*red)[RED_STRIDE] =
            (float (*)[RED_STRIDE])(smem + (size_t)(kset - 1) * RED_BYTES);
#pragma unroll
        for (int mf = 0; mf < 2; ++mf)
#pragma unroll
            for (int nf = 0; nf < 8; ++nf) {
                const int rl = wm + mf * 16 + r0;
                const int cl = nf * 8 + cpos;
                red[rl][cl]         = acc[mf][nf][0];
                red[rl][cl + 1]     = acc[mf][nf][1];
                red[rl + 8][cl]     = acc[mf][nf][2];
                red[rl + 8][cl + 1] = acc[mf][nf][3];
            }
    }
    __syncthreads();

    if (kset == 0) {
        float* __restrict__ G = out + EPHI_SZ;
        float (*red0)[RED_STRIDE] = (float (*)[RED_STRIDE])(smem);
        float (*red1)[RED_STRIDE] = (float (*)[RED_STRIDE])(smem + RED_BYTES);
        float (*red2)[RED_STRIDE] = (float (*)[RED_STRIDE])(smem + 2 * RED_BYTES);
#pragma unroll
        for (int mf = 0; mf < 2; ++mf)
#pragma unroll
            for (int nf = 0; nf < 8; ++nf)
#pragma unroll
                for (int r2 = 0; r2 < 4; ++r2) {
                    const int rl = wm + mf * 16 + r0 + (r2 >> 1) * 8;
                    const int cl = nf * 8 + cpos + (r2 & 1);
                    const int gi = i0 + rl;
                    const int gj = j0 + cl;
                    float val = acc[mf][nf][r2]
                              + red0[rl][cl] + red1[rl][cl] + red2[rl][cl];
                    if (gi == gj) val = g_diag[gi];
                    G[(size_t)gi * KQ + gj] = val;
                    G[(size_t)gj * KQ + gi] = val;
                }
    }
}

// ---------------------------------------------------------------------------
extern "C" void kernel_launch(void* const* d_in, const int* in_sizes, int n_in,
                              void* d_out, int out_size)
{
    const float* X           = (const float*)d_in[0];
    const float* z           = (const float*)d_in[1];
    const float* weight      = (const float*)d_in[2];
    const float* mu          = (const float*)d_in[3];
    const float* stdv        = (const float*)d_in[4];
    const float* alpha       = (const float*)d_in[5];
    const float* var_mu_w    = (const float*)d_in[6];
    const float* var_sigma_w = (const float*)d_in[7];
    float* out = (float*)d_out;

    cudaFuncSetAttribute(syrk_mma_kernel,
                         cudaFuncAttributeMaxDynamicSharedMemorySize, SMEM_SYRK);

    dim3 egrid(KQ / 256, N_PTS / 32);
    ephi_kernel<<<egrid, 256>>>(X, z, weight, mu, stdv, alpha,
                                var_mu_w, var_sigma_w, out);

    diag_reduce_kernel<<<4, 256>>>();

    syrk_mma_kernel<<<136, 256, SMEM_SYRK>>>(out);
}

// round 16
// speedup vs baseline: 1.8099x; 1.0420x over previous
#include <cuda_runtime.h>
#include <cuda_bf16.h>
#include <math.h>
#include <stdint.h>

#define N_PTS   8192
#define D_DIM   8
#define K_DIM   64
#define Q_DIM   16
#define KQ      1024
#define TWO_PI  6.283185307179586f

#define EPHI_SZ (N_PTS * KQ)    // 8388608
#define G_SZ    (KQ * KQ)       // 1048576
// d_out layout: [E_phi (N,KQ) | G (KQ,KQ) | E_cos_sq (N,KQ)]

// -------- device scratch --------
__device__ float g_dpart[256 * KQ];
__device__ __nv_bfloat16 g_hi[(size_t)KQ * N_PTS];
__device__ __nv_bfloat16 g_lo[(size_t)KQ * N_PTS];

// ---------------------------------------------------------------------------
// helpers
// ---------------------------------------------------------------------------
__device__ __forceinline__ uint32_t smem_u32(const void* p) {
    uint32_t a;
    asm("{ .reg .u64 t; cvta.to.shared.u64 t, %1; cvt.u32.u64 %0, t; }"
        : "=r"(a) : "l"(p));
    return a;
}
__device__ __forceinline__ void cp16(uint32_t dst, const void* src) {
    asm volatile("cp.async.cg.shared.global [%0], [%1], 16;"
                 :: "r"(dst), "l"(src));
}
__device__ __forceinline__ void cp_commit() {
    asm volatile("cp.async.commit_group;" ::: "memory");
}
template <int N>
__device__ __forceinline__ void cp_wait() {
    asm volatile("cp.async.wait_group %0;" :: "n"(N) : "memory");
}
__device__ __forceinline__ void bar_sync(int id, int cnt) {
    asm volatile("bar.sync %0, %1;" :: "r"(id), "r"(cnt) : "memory");
}
__device__ __forceinline__ void ldsm4(uint32_t* r, uint32_t addr) {
    asm volatile("ldmatrix.sync.aligned.m8n8.x4.shared.b16 {%0,%1,%2,%3}, [%4];"
                 : "=r"(r[0]), "=r"(r[1]), "=r"(r[2]), "=r"(r[3]) : "r"(addr));
}
__device__ __forceinline__ void mma_bf16(float* c, const uint32_t* a,
                                         uint32_t b0, uint32_t b1) {
    asm volatile(
        "mma.sync.aligned.m16n8k16.row.col.f32.bf16.bf16.f32 "
        "{%0,%1,%2,%3}, {%4,%5,%6,%7}, {%8,%9}, {%0,%1,%2,%3};"
        : "+f"(c[0]), "+f"(c[1]), "+f"(c[2]), "+f"(c[3])
        : "r"(a[0]), "r"(a[1]), "r"(a[2]), "r"(a[3]), "r"(b0), "r"(b1));
}

// swizzled offset within a 64B-row buffer (16B granules)
__device__ __forceinline__ uint32_t swz(int row, int seg) {
    return (uint32_t)(row * 64 + ((seg ^ ((row >> 1) & 3)) << 4));
}

// ---------------------------------------------------------------------------
// Kernel 1: fused E_phi, E_cos_sq, split-bf16 transposed hi/lo, diag partials.
// Inner loop strength-reduced via quadratic expansion:
//   phase = sum_d ew*x - pc,  s = c2 + sum_d (cc*x^2 + czn*x)
// with pc = sum ew*zz, c2 = sum cc*zz^2, czn = -2*cc*zz hoisted per thread.
// ---------------------------------------------------------------------------
__global__ void __launch_bounds__(256) ephi_kernel(const float* __restrict__ X,
                            const float* __restrict__ z,
                            const float* __restrict__ weight,
                            const float* __restrict__ mu,
                            const float* __restrict__ stdv,
                            const float* __restrict__ alpha,
                            const float* __restrict__ var_mu_w,
                            const float* __restrict__ var_sigma_w,
                            float* __restrict__ out)
{
    const int tid = threadIdx.x;
    const int kq0 = blockIdx.x * 256;
    const int kq  = kq0 + tid;
    const int n0  = blockIdx.y * 32;

    __shared__ float Xs[256];                  // 2*pi*x
    __shared__ float Xs2[256];                 // (2*pi*x)^2
    __shared__ float s_mp[128], s_sp[128];
    __shared__ __nv_bfloat16 s_hi[256][34];
    __shared__ __nv_bfloat16 s_lo[256][34];

    {
        float xv = TWO_PI * X[n0 * D_DIM + tid];
        Xs[tid]  = xv;
        Xs2[tid] = xv * xv;
    }
    if (tid < 128) {
        s_mp[tid] = 1.0f / (mu[tid] + 1e-8f);
        s_sp[tid] = 1.0f / (TWO_PI * stdv[tid] + 1e-8f);
    }
    __syncthreads();

    const int q = kq & (Q_DIM - 1);
    float ew[D_DIM], cc[D_DIM], czn[D_DIM];
    float pc = 0.0f, c2 = 0.0f;
#pragma unroll
    for (int d = 0; d < D_DIM; ++d) {
        const float mp = s_mp[d * Q_DIM + q];
        const float sp = s_sp[d * Q_DIM + q];
        const float e  = mp + sp * var_mu_w[d * KQ + kq];
        const float c  = sp * sp * var_sigma_w[d * KQ + kq];
        const float zv = TWO_PI * z[d * KQ + kq];
        ew[d]  = e;
        cc[d]  = c;
        czn[d] = -2.0f * c * zv;
        pc     = fmaf(e, zv, pc);
        c2     = fmaf(c, zv * zv, c2);
    }
    const float a    = alpha[kq];
    const float coef = 2.0f * weight[q] * (1.0f / (float)K_DIM);
    const float sq   = sqrtf(coef);
    const float amp  = a - pc;                 // fold pc into the cos argument

    float* __restrict__ outE = out;
    float* __restrict__ outC = out + EPHI_SZ + G_SZ;

    float dsum = 0.0f;
#pragma unroll 4
    for (int r = 0; r < 32; ++r) {
        float phase = amp, s = c2;
#pragma unroll
        for (int d = 0; d < D_DIM; ++d) {
            const float xv  = Xs [r * D_DIM + d];
            const float xv2 = Xs2[r * D_DIM + d];
            phase = fmaf(ew[d],  xv,  phase);
            s     = fmaf(cc[d],  xv2, s);
            s     = fmaf(czn[d], xv,  s);
        }
        float cw    = __cosf(phase);
        float decay = __expf(-0.5f * s);

        const int n = n0 + r;
        float E = sq * decay * cw;
        outE[n * KQ + kq] = E;

        float d2  = decay * decay;
        float d4  = d2 * d2;
        float c2w = 2.0f * cw * cw - 1.0f;
        float ecs = coef * (0.5f + 0.5f * d4 * c2w);
        outC[n * KQ + kq] = ecs;
        dsum += ecs;

        __nv_bfloat16 h = __float2bfloat16(E);
        s_hi[tid][r] = h;
        s_lo[tid][r] = __float2bfloat16(E - __bfloat162float(h));
    }
    g_dpart[blockIdx.y * KQ + kq] = dsum;
    __syncthreads();

    uint32_t* __restrict__ H = (uint32_t*)g_hi;
    uint32_t* __restrict__ L = (uint32_t*)g_lo;
#pragma unroll
    for (int i = 0; i < 16; ++i) {
        int v   = tid + i * 256;
        int row = v >> 4;
        int seg = v & 15;
        uint32_t h2 = *(const uint32_t*)&s_hi[row][seg * 2];
        uint32_t l2 = *(const uint32_t*)&s_lo[row][seg * 2];
        size_t o = ((size_t)(kq0 + row) * N_PTS + n0) / 2 + seg;
        H[o] = h2;
        L[o] = l2;
    }
}

// ---------------------------------------------------------------------------
// Kernel 2: SYRK — R8 schedule + pair-shared B buffers + fused diag epilogue.
// 136 upper-triangular 64x64 tiles, 256 threads = 8 warps.
// Warp (ms, kset): ms = m-half (32 rows), kset = k-quarter (32 of 128 per sc).
// A: warp-private, stage = AHI 2KB | ALO 2KB, x2 stages = 8KB/warp (64KB).
// B: SHARED per kset pair, stage = BHI 4KB | BLO 4KB, x2 stages = 16KB/kset
//    (64KB). Each pair-warp loads its 32-row half of B.
// Per sc: cp_wait<1>; bar(pair); batched ldsm; bar(pair); refill+commit;
// hh/hl/lh chains. Total smem 128KB. NO CTA-wide mainloop barrier.
// Epilogue: 4-set smem reduce + write/mirror; diagonal tiles reduce g_dpart.
// ---------------------------------------------------------------------------
#define A_STAGE  4096                 // AHI 2048 | ALO 2048
#define A_WBUF   (2 * A_STAGE)        // 8192 per warp
#define B_REGION (8 * A_WBUF)         // 65536: B region base
#define B_STAGE  8192                 // BHI 4096 | BLO 4096
#define B_KBUF   (2 * B_STAGE)        // 16384 per kset
#define SMEM_SYRK (B_REGION + 4 * B_KBUF)   // 131072
#define NSC 64
#define RED_STRIDE 65
#define RED_BYTES (64 * RED_STRIDE * 4)   // 16640
#define SDIAG_OFF (3 * RED_BYTES)         // 49920

// A refill: 32 rows x 32k, hi+lo = 256 16B-chunks (8 cp per lane)
__device__ __forceinline__ void load_A(uint32_t astage, int i0r,
                                       size_t koff, int lane)
{
#pragma unroll
    for (int it = 0; it < 8; ++it) {
        int cid = it * 32 + lane;
        int h   = cid >> 7;
        int rc  = cid & 127;
        int row = rc >> 2;
        int seg = rc & 3;
        uint32_t dst = astage + (uint32_t)(h ? 2048 : 0) + swz(row, seg);
        const __nv_bfloat16* base = h ? g_lo : g_hi;
        cp16(dst, (const char*)(base + (size_t)(i0r + row) * N_PTS + koff) + seg * 16);
    }
}
// B-half refill: 32 rows (ms half) x 32k, hi+lo = 256 chunks (8 cp per lane)
__device__ __forceinline__ void load_Bhalf(uint32_t bstage, int j0, int ms,
                                           size_t koff, int lane)
{
#pragma unroll
    for (int it = 0; it < 8; ++it) {
        int cid = it * 32 + lane;
        int h   = cid >> 7;
        int rc  = cid & 127;
        int row = (rc >> 2) + ms * 32;
        int seg = rc & 3;
        uint32_t dst = bstage + (uint32_t)(h ? 4096 : 0) + swz(row, seg);
        const __nv_bfloat16* base = h ? g_lo : g_hi;
        cp16(dst, (const char*)(base + (size_t)(j0 + row) * N_PTS + koff) + seg * 16);
    }
}

__global__ void __launch_bounds__(256, 1) syrk_mma_kernel(float* __restrict__ out)
{
    extern __shared__ __align__(1024) char smem[];
    const uint32_t sbase = smem_u32(smem);
    const int tid  = threadIdx.x;
    const int lane = tid & 31;
    const int wid  = tid >> 5;
    const int ms   = wid & 1;               // m-half
    const int kset = wid >> 1;              // k-quarter
    const int wm   = ms * 32;
    const int barid = 1 + kset;             // named barrier per pair
    const uint32_t abase = sbase + (uint32_t)wid * A_WBUF;
    const uint32_t bbase = sbase + B_REGION + (uint32_t)kset * B_KBUF;

    int b = blockIdx.x, ti = 0, rem = b;
    while (rem >= 16 - ti) { rem -= 16 - ti; ++ti; }
    const int tj = ti + rem;
    const int i0 = ti * 64;
    const int j0 = tj * 64;
    const int i0r = i0 + wm;
    const bool diagTile = (ti == tj);

    // ldmatrix addresses
    const int g  = lane >> 3;
    const int rr = lane & 7;
    uint32_t a_addr[2][2], b_addr[4][2];
#pragma unroll
    for (int mf = 0; mf < 2; ++mf)
#pragma unroll
        for (int ks = 0; ks < 2; ++ks) {
            int m   = mf * 16 + rr + (g & 1) * 8;
            int seg = (g >> 1) + ks * 2;
            a_addr[mf][ks] = abase + swz(m, seg);              // AHI
        }
#pragma unroll
    for (int nf2 = 0; nf2 < 4; ++nf2)
#pragma unroll
        for (int ks = 0; ks < 2; ++ks) {
            int n   = nf2 * 16 + rr + (g >> 1) * 8;
            int seg = (g & 1) + ks * 2;
            b_addr[nf2][ks] = bbase + swz(n, seg);             // BHI
        }

    float acc[2][8][4];
#pragma unroll
    for (int mf = 0; mf < 2; ++mf)
#pragma unroll
        for (int nf = 0; nf < 8; ++nf)
#pragma unroll
            for (int r2 = 0; r2 < 4; ++r2) acc[mf][nf][r2] = 0.0f;

    const size_t kbase = (size_t)kset * 32;
    load_A(abase,           i0r,     kbase,       lane);
    load_Bhalf(bbase,       j0, ms,  kbase,       lane);
    cp_commit();
    load_A(abase + A_STAGE, i0r,     kbase + 128, lane);
    load_Bhalf(bbase + B_STAGE, j0, ms, kbase + 128, lane);
    cp_commit();

    for (int sc = 0; sc < NSC; ++sc) {
        cp_wait<1>();                         // own half of chunk sc complete
        bar_sync(barid, 64);                  // partner's half visible too
        const uint32_t soA = (uint32_t)(sc & 1) * A_STAGE;
        const uint32_t soB = (uint32_t)(sc & 1) * B_STAGE;

        // batched ldsm (R8-proven order), both ks
        uint32_t ah[2][2][4], al[2][2][4], bh[2][4][4], bl[2][4][4];
#pragma unroll
        for (int ks = 0; ks < 2; ++ks) {
            ldsm4(ah[ks][0], a_addr[0][ks] + soA);
            ldsm4(ah[ks][1], a_addr[1][ks] + soA);
            ldsm4(al[ks][0], a_addr[0][ks] + soA + 2048);
            ldsm4(al[ks][1], a_addr[1][ks] + soA + 2048);
#pragma unroll
            for (int nf2 = 0; nf2 < 4; ++nf2) {
                ldsm4(bh[ks][nf2], b_addr[nf2][ks] + soB);
                ldsm4(bl[ks][nf2], b_addr[nf2][ks] + soB + 4096);
            }
        }
        bar_sync(barid, 64);                  // pair done reading this stage

        // refill this stage for chunk sc+2 (own halves), single commit
        if (sc + 2 < NSC) {
            const size_t knext = kbase + (size_t)(sc + 2) * 128;
            load_A(abase + soA, i0r, knext, lane);
            load_Bhalf(bbase + soB, j0, ms, knext, lane);
        }
        cp_commit();

#pragma unroll
        for (int ks = 0; ks < 2; ++ks) {
            // hh chain
#pragma unroll
            for (int mf = 0; mf < 2; ++mf)
#pragma unroll
                for (int nf = 0; nf < 8; ++nf)
                    mma_bf16(acc[mf][nf], ah[ks][mf],
                             bh[ks][nf >> 1][(nf & 1) * 2],
                             bh[ks][nf >> 1][(nf & 1) * 2 + 1]);
            // hl chain
#pragma unroll
            for (int mf = 0; mf < 2; ++mf)
#pragma unroll
                for (int nf = 0; nf < 8; ++nf)
                    mma_bf16(acc[mf][nf], ah[ks][mf],
                             bl[ks][nf >> 1][(nf & 1) * 2],
                             bl[ks][nf >> 1][(nf & 1) * 2 + 1]);
            // lh chain
#pragma unroll
            for (int mf = 0; mf < 2; ++mf)
#pragma unroll
                for (int nf = 0; nf < 8; ++nf)
                    mma_bf16(acc[mf][nf], al[ks][mf],
                             bh[ks][nf >> 1][(nf & 1) * 2],
                             bh[ks][nf >> 1][(nf & 1) * 2 + 1]);
        }
    }

    // ---- epilogue: 4-set reduction + write (tile, mirror, fused diag) ----
    __syncthreads();                          // all warps done with bufs
    const int r0   = lane >> 2;
    const int cpos = (lane & 3) * 2;
    float (*sdiag)[64] = (float (*)[64])(smem + SDIAG_OFF);

    if (diagTile) {                           // per-column sums of E_cos_sq
        const int c  = tid & 63;
        const int gq = tid >> 6;              // 0..3
        float s = 0.0f;
#pragma unroll 8
        for (int p = gq * 64; p < gq * 64 + 64; ++p)
            s += g_dpart[p * KQ + j0 + c];
        sdiag[gq][c] = s;
    }

    if (kset >= 1) {
        float (*red)[RED_STRIDE] =
            (float (*)[RED_STRIDE])(smem + (size_t)(kset - 1) * RED_BYTES);
#pragma unroll
        for (int mf = 0; mf < 2; ++mf)
#pragma unroll
            for (int nf = 0; nf < 8; ++nf) {
                const int rl = wm + mf * 16 + r0;
                const int cl = nf * 8 + cpos;
                red[rl][cl]         = acc[mf][nf][0];
                red[rl][cl + 1]     = acc[mf][nf][1];
                red[rl + 8][cl]     = acc[mf][nf][2];
                red[rl + 8][cl + 1] = acc[mf][nf][3];
            }
    }
    __syncthreads();

    if (kset == 0) {
        float* __restrict__ G = out + EPHI_SZ;
        float (*red0)[RED_STRIDE] = (float (*)[RED_STRIDE])(smem);
        float (*red1)[RED_STRIDE] = (float (*)[RED_STRIDE])(smem + RED_BYTES);
        float (*red2)[RED_STRIDE] = (float (*)[RED_STRIDE])(smem + 2 * RED_BYTES);
#pragma unroll
        for (int mf = 0; mf < 2; ++mf)
#pragma unroll
            for (int nf = 0; nf < 8; ++nf)
#pragma unroll
                for (int r2 = 0; r2 < 4; ++r2) {
                    const int rl = wm + mf * 16 + r0 + (r2 >> 1) * 8;
                    const int cl = nf * 8 + cpos + (r2 & 1);
                    const int gi = i0 + rl;
                    const int gj = j0 + cl;
                    float val = acc[mf][nf][r2]
                              + red0[rl][cl] + red1[rl][cl] + red2[rl][cl];
                    if (diagTile && gi == gj)
                        val = sdiag[0][cl] + sdiag[1][cl]
                            + sdiag[2][cl] + sdiag[3][cl];
                    G[(size_t)gi * KQ + gj] = val;
                    G[(size_t)gj * KQ + gi] = val;
                }
    }
}

// ---------------------------------------------------------------------------
extern "C" void kernel_launch(void* const* d_in, const int* in_sizes, int n_in,
                              void* d_out, int out_size)
{
    const float* X           = (const float*)d_in[0];
    const float* z           = (const float*)d_in[1];
    const float* weight      = (const float*)d_in[2];
    const float* mu          = (const float*)d_in[3];
    const float* stdv        = (const float*)d_in[4];
    const float* alpha       = (const float*)d_in[5];
    const float* var_mu_w    = (const float*)d_in[6];
    const float* var_sigma_w = (const float*)d_in[7];
    float* out = (float*)d_out;

    cudaFuncSetAttribute(syrk_mma_kernel,
                         cudaFuncAttributeMaxDynamicSharedMemorySize, SMEM_SYRK);

    dim3 egrid(KQ / 256, N_PTS / 32);
    ephi_kernel<<<egrid, 256>>>(X, z, weight, mu, stdv, alpha,
                                var_mu_w, var_sigma_w, out);

    syrk_mma_kernel<<<136, 256, SMEM_SYRK>>>(out);
}